// round 16
// baseline (speedup 1.0000x reference)
#include <cuda_runtime.h>
#include <cuda.h>
#include <cuda_fp16.h>
#include <cstdint>

// ---------------- problem constants ----------------
#define N_TOK 8192
#define TOPK  2
#define NEXP  8
#define HDIM  2048
#define IDIM  1408
#define NSLOT (N_TOK * TOPK)           // 16384
#define BM    128
#define MAXT  (NSLOT / BM + NEXP)      // 136 worst-case M tiles

// ---------------- GEMM pipeline constants ----------------
#define KC      64                      // K elements per chunk (128 bytes fp16)
#define STAGES  3
#define A_BYTES (128 * KC * 2)          // 16384: A tile 128 rows
#define B_BYTES (128 * KC * 2)          // 16384: B tile 128 rows (2 halves of 64)
#define STAGE_B (A_BYTES + B_BYTES)     // 32768
#define SMEM_DYN (STAGES * STAGE_B + 1024)   // ~99 KB -> 2 CTAs/SM

// ---------------- scratch (static device globals) ----------------
__device__ __align__(16) __half g_ax   [(size_t)NSLOT * HDIM];            // sorted A, fp16
__device__ __align__(16) __half g_w1t  [(size_t)NEXP * 2 * IDIM * HDIM];  // [E][2816][2048]
__device__ __align__(16) __half g_w2t  [(size_t)NEXP * HDIM * IDIM];      // [E][2048][1408]
__device__ __align__(16) __half g_inter[(size_t)NSLOT * IDIM];            // fp16 SwiGLU out
__device__ __align__(16) __half g_outs [(size_t)NSLOT * HDIM];            // fp16 expert out
__device__ int g_pos2slot[NSLOT];
__device__ int g_slot2pos[NSLOT];
__device__ int g_tile_e[MAXT], g_tile_r0[MAXT], g_tile_rows[MAXT];
__device__ int g_ntiles;

// ---------------- PTX helpers ----------------
__device__ __forceinline__ uint32_t smem_u32(const void* p) {
    uint32_t a;
    asm("{ .reg .u64 t; cvta.to.shared.u64 t, %1; cvt.u32.u64 %0, t; }"
        : "=r"(a) : "l"(p));
    return a;
}
__device__ __forceinline__ void mbar_init(uint32_t a, uint32_t cnt) {
    asm volatile("mbarrier.init.shared.b64 [%0], %1;" :: "r"(a), "r"(cnt) : "memory");
}
__device__ __forceinline__ void mbar_expect(uint32_t a, uint32_t bytes) {
    asm volatile("mbarrier.arrive.expect_tx.shared.b64 _, [%0], %1;"
                 :: "r"(a), "r"(bytes) : "memory");
}
__device__ __forceinline__ void mbar_arrive(uint32_t a) {
    asm volatile("mbarrier.arrive.shared.b64 _, [%0];" :: "r"(a) : "memory");
}
__device__ __forceinline__ void mbar_wait(uint32_t a, uint32_t parity) {
    asm volatile(
        "{\n\t.reg .pred P;\n\t"
        "WL%=:\n\t"
        "mbarrier.try_wait.parity.acquire.cta.shared::cta.b64 P, [%0], %1, 0x989680;\n\t"
        "@P bra WD%=;\n\t"
        "bra WL%=;\n\t"
        "WD%=:\n\t}"
        :: "r"(a), "r"(parity) : "memory");
}
__device__ __forceinline__ void tma3d(uint32_t dst, const CUtensorMap* tm,
                                      int x, int y, int z, uint32_t mbar) {
    asm volatile(
        "cp.async.bulk.tensor.3d.shared::cta.global.tile.mbarrier::complete_tx::bytes "
        "[%0], [%1, {%2, %3, %4}], [%5];"
        :: "r"(dst), "l"(tm), "r"(x), "r"(y), "r"(z), "r"(mbar) : "memory");
}
__device__ __forceinline__ void ldsm4(uint32_t r[4], uint32_t addr) {
    asm volatile("ldmatrix.sync.aligned.m8n8.x4.shared.b16 {%0,%1,%2,%3}, [%4];"
                 : "=r"(r[0]), "=r"(r[1]), "=r"(r[2]), "=r"(r[3]) : "r"(addr));
}
__device__ __forceinline__ void mma16816(float c[4], const uint32_t a[4],
                                         uint32_t b0, uint32_t b1) {
    asm volatile(
        "mma.sync.aligned.m16n8k16.row.col.f32.f16.f16.f32 "
        "{%0,%1,%2,%3}, {%4,%5,%6,%7}, {%8,%9}, {%0,%1,%2,%3};"
        : "+f"(c[0]), "+f"(c[1]), "+f"(c[2]), "+f"(c[3])
        : "r"(a[0]), "r"(a[1]), "r"(a[2]), "r"(a[3]), "r"(b0), "r"(b1));
}
__device__ __forceinline__ uint32_t sw128(uint32_t off) {
    return off ^ ((off >> 3) & 0x70);
}

// ---------------- routing ----------------
__global__ void route_kernel(const int* __restrict__ topk_idx) {
    __shared__ int cnt[NEXP];
    __shared__ int cur[NEXP];
    int tid = threadIdx.x;
    if (tid < NEXP) cnt[tid] = 0;
    __syncthreads();
    for (int s = tid; s < NSLOT; s += blockDim.x)
        atomicAdd(&cnt[topk_idx[s]], 1);
    __syncthreads();
    if (tid == 0) {
        int off = 0, t = 0;
        for (int e = 0; e < NEXP; e++) {
            cur[e] = off;
            int c = cnt[e];
            for (int r = 0; r < c; r += BM) {
                g_tile_e[t] = e;
                g_tile_r0[t] = off + r;
                g_tile_rows[t] = (c - r < BM) ? (c - r) : BM;
                t++;
            }
            off += c;
        }
        g_ntiles = t;
    }
    __syncthreads();
    for (int s = tid; s < NSLOT; s += blockDim.x) {
        int p = atomicAdd(&cur[topk_idx[s]], 1);
        g_pos2slot[p] = s;
        g_slot2pos[s] = p;
    }
}

// ---------------- gather + fp16 convert of A ----------------
__global__ void gather_x_kernel(const float* __restrict__ x) {
    int pos = blockIdx.x;
    int token = g_pos2slot[pos] / TOPK;
    const float4* src = (const float4*)(x + (size_t)token * HDIM);
    uint2* dst = (uint2*)(g_ax + (size_t)pos * HDIM);
    for (int c = threadIdx.x; c < HDIM / 4; c += blockDim.x) {
        float4 v = src[c];
        __half2 a = __floats2half2_rn(v.x, v.y);
        __half2 b = __floats2half2_rn(v.z, v.w);
        uint2 u;
        u.x = *(uint32_t*)&a;
        u.y = *(uint32_t*)&b;
        dst[c] = u;
    }
}

// ---------------- weight transpose + fp16 convert (64x64 tiles) -------------
template <int SRC_ROW, int DST_ROW>
__device__ __forceinline__ void transpose64(const float* __restrict__ src,
                                            __half* __restrict__ dst,
                                            int k0, int n0) {
    __shared__ float t[64][65];   // t[n][k]
    int tid = threadIdx.x;        // 256
#pragma unroll
    for (int p = 0; p < 4; p++) {
        int kr = p * 16 + (tid >> 4);
        int nc = (tid & 15) * 4;
        float4 v = *(const float4*)(src + (size_t)(k0 + kr) * SRC_ROW + n0 + nc);
        t[nc + 0][kr] = v.x;
        t[nc + 1][kr] = v.y;
        t[nc + 2][kr] = v.z;
        t[nc + 3][kr] = v.w;
    }
    __syncthreads();
    int nr = tid >> 5, tx = tid & 31;
#pragma unroll
    for (int p = 0; p < 8; p++) {
        int n = p * 8 + nr;
        __half2 h = __floats2half2_rn(t[n][2 * tx], t[n][2 * tx + 1]);
        *(__half2*)(dst + (size_t)(n0 + n) * DST_ROW + k0 + 2 * tx) = h;
    }
}
// gate_up [E][H][2I] fp32 -> g_w1t [E][2I][H] fp16.
__global__ __launch_bounds__(256) void transpose_w1_kernel(const float* __restrict__ w) {
    int e = blockIdx.z;
    transpose64<2 * IDIM, HDIM>(w + (size_t)e * HDIM * (2 * IDIM),
                                g_w1t + (size_t)e * (2 * IDIM) * HDIM,
                                blockIdx.x * 64, blockIdx.y * 64);
}
// down [E][I][H] fp32 -> g_w2t [E][H][I] fp16.
__global__ __launch_bounds__(256) void transpose_w2_kernel(const float* __restrict__ w) {
    int e = blockIdx.z;
    transpose64<HDIM, IDIM>(w + (size_t)e * IDIM * HDIM,
                            g_w2t + (size_t)e * HDIM * IDIM,
                            blockIdx.x * 64, blockIdx.y * 64);
}

// ---------------- HMMA mainloop: M=128 x N=(64+64), 3-stage, 2 CTAs/SM ------
// TMA refill duty ROTATES across warps (warp == c % 8) so the empty-barrier
// straggler wait doesn't land on the same warp every chunk.
__device__ __forceinline__ void hmma_mainloop(
    uint32_t sb, const CUtensorMap* tA, const CUtensorMap* tB,
    int row0, int y0, int y1, int ez, int nchunks, float acc[2][8][4])
{
    __shared__ __align__(8) unsigned long long mbar[2 * STAGES];
    int tid = threadIdx.x;
    uint32_t fb = smem_u32(&mbar[0]);
    uint32_t eb = smem_u32(&mbar[STAGES]);
    if (tid == 0) {
        for (int s = 0; s < STAGES; s++) {
            mbar_init(fb + 8u * s, 1);
            mbar_init(eb + 8u * s, 256);
        }
    }
    __syncthreads();
    if (tid == 0) {
        int npre = (STAGES < nchunks) ? STAGES : nchunks;
        for (int c = 0; c < npre; c++) {
            uint32_t st = sb + c * STAGE_B;
            mbar_expect(fb + 8u * c, STAGE_B);
            tma3d(st,                          tA, c * KC, row0, 0,  fb + 8u * c);
            tma3d(st + A_BYTES,                tB, c * KC, y0,   ez, fb + 8u * c);
            tma3d(st + A_BYTES + B_BYTES / 2,  tB, c * KC, y1,   ez, fb + 8u * c);
        }
    }
    int lane = tid & 31, warp = tid >> 5;
    int wm = warp >> 1, wn = warp & 1;               // 4m x 2n warp grid
    int aRow = wm * 32 + (lane & 15);                // + mt*16
    int aKb  = (lane >> 4) << 4;                     // + ks*32
    int bRow = wn * 32 + (lane & 7) + ((lane >> 4) << 3);  // + pp*16 (+64 half1)
    int bKb  = ((lane >> 3) & 1) << 4;               // + ks*32

    int s = 0, parity = 0;
    for (int c = 0; c < nchunks; c++) {
        uint32_t st = sb + s * STAGE_B;
        mbar_wait(fb + 8u * s, parity);
        uint32_t aB = st, bB = st + A_BYTES;
#pragma unroll
        for (int ks = 0; ks < KC / 16; ks++) {
            uint32_t a[2][4];
#pragma unroll
            for (int mt = 0; mt < 2; mt++) {
                uint32_t off = (uint32_t)(aRow + mt * 16) * 128 + aKb + ks * 32;
                ldsm4(a[mt], aB + sw128(off));
            }
#pragma unroll
            for (int half = 0; half < 2; half++) {
#pragma unroll
                for (int pp = 0; pp < 2; pp++) {
                    uint32_t off = (uint32_t)(half * 64 + bRow + pp * 16) * 128
                                   + bKb + ks * 32;
                    uint32_t b[4];
                    ldsm4(b, bB + sw128(off));
                    int nt = half * 4 + pp * 2;
                    mma16816(acc[0][nt],     a[0], b[0], b[1]);
                    mma16816(acc[0][nt + 1], a[0], b[2], b[3]);
                    mma16816(acc[1][nt],     a[1], b[0], b[1]);
                    mma16816(acc[1][nt + 1], a[1], b[2], b[3]);
                }
            }
        }
        mbar_arrive(eb + 8u * s);
        if (warp == (c & 7) && lane == 0 && c + STAGES < nchunks) {
            mbar_wait(eb + 8u * s, parity);
            int cn = c + STAGES;
            mbar_expect(fb + 8u * s, STAGE_B);
            tma3d(st,                         tA, cn * KC, row0, 0,  fb + 8u * s);
            tma3d(st + A_BYTES,               tB, cn * KC, y0,   ez, fb + 8u * s);
            tma3d(st + A_BYTES + B_BYTES / 2, tB, cn * KC, y1,   ez, fb + 8u * s);
        }
        if (++s == STAGES) { s = 0; parity ^= 1; }
    }
}

// ---------------- GEMM1: A_sorted @ w1t (gate+up) + fused SwiGLU ------------
__global__ __launch_bounds__(256, 2) void gemm1_tc(
    const __grid_constant__ CUtensorMap tA,
    const __grid_constant__ CUtensorMap tB)
{
    int t = blockIdx.y;
    if (t >= g_ntiles) return;
    int e = g_tile_e[t], row0 = g_tile_r0[t], rows = g_tile_rows[t];
    int c0 = blockIdx.x * 64;
    extern __shared__ __align__(1024) char dsm[];
    uint32_t sb = (smem_u32(dsm) + 1023u) & ~1023u;

    float acc[2][8][4];
#pragma unroll
    for (int i = 0; i < 2; i++)
#pragma unroll
        for (int j = 0; j < 8; j++)
#pragma unroll
            for (int q = 0; q < 4; q++) acc[i][j][q] = 0.f;

    hmma_mainloop(sb, &tA, &tB, row0, c0, IDIM + c0, e, HDIM / KC, acc);

    int lane = threadIdx.x & 31, warp = threadIdx.x >> 5;
    int wm = warp >> 1, wn = warp & 1;
#pragma unroll
    for (int mt = 0; mt < 2; mt++) {
#pragma unroll
        for (int nt = 0; nt < 4; nt++) {
            int col = c0 + wn * 32 + nt * 8 + 2 * (lane & 3);
            int r_lo = wm * 32 + mt * 16 + (lane >> 2);
            float g0 = acc[mt][nt][0], g1 = acc[mt][nt][1];
            float u0 = acc[mt][nt + 4][0], u1 = acc[mt][nt + 4][1];
            if (r_lo < rows) {
                float o0 = u0 * (g0 / (1.f + __expf(-g0)));
                float o1 = u1 * (g1 / (1.f + __expf(-g1)));
                __half2 p = __floats2half2_rn(o0, o1);
                *(__half2*)(g_inter + (size_t)(row0 + r_lo) * IDIM + col) = p;
            }
            int r_hi = r_lo + 8;
            g0 = acc[mt][nt][2]; g1 = acc[mt][nt][3];
            u0 = acc[mt][nt + 4][2]; u1 = acc[mt][nt + 4][3];
            if (r_hi < rows) {
                float o0 = u0 * (g0 / (1.f + __expf(-g0)));
                float o1 = u1 * (g1 / (1.f + __expf(-g1)));
                __half2 p = __floats2half2_rn(o0, o1);
                *(__half2*)(g_inter + (size_t)(row0 + r_hi) * IDIM + col) = p;
            }
        }
    }
}

// ---------------- GEMM2: g_inter @ w2t -> g_outs (fp16) ---------------------
__global__ __launch_bounds__(256, 2) void gemm2_tc(
    const __grid_constant__ CUtensorMap tA,
    const __grid_constant__ CUtensorMap tB)
{
    int t = blockIdx.y;
    if (t >= g_ntiles) return;
    int e = g_tile_e[t], row0 = g_tile_r0[t], rows = g_tile_rows[t];
    int n0 = blockIdx.x * 128;
    extern __shared__ __align__(1024) char dsm[];
    uint32_t sb = (smem_u32(dsm) + 1023u) & ~1023u;

    float acc[2][8][4];
#pragma unroll
    for (int i = 0; i < 2; i++)
#pragma unroll
        for (int j = 0; j < 8; j++)
#pragma unroll
            for (int q = 0; q < 4; q++) acc[i][j][q] = 0.f;

    hmma_mainloop(sb, &tA, &tB, row0, n0, n0 + 64, e, IDIM / KC, acc);

    int lane = threadIdx.x & 31, warp = threadIdx.x >> 5;
    int wm = warp >> 1, wn = warp & 1;
#pragma unroll
    for (int mt = 0; mt < 2; mt++) {
#pragma unroll
        for (int nt = 0; nt < 8; nt++) {
            int colh = (nt < 4) ? (wn * 32 + nt * 8) : (64 + wn * 32 + (nt - 4) * 8);
            int col = n0 + colh + 2 * (lane & 3);
            int r_lo = wm * 32 + mt * 16 + (lane >> 2);
            if (r_lo < rows) {
                __half2 v = __floats2half2_rn(acc[mt][nt][0], acc[mt][nt][1]);
                *(__half2*)(g_outs + (size_t)(row0 + r_lo) * HDIM + col) = v;
            }
            int r_hi = r_lo + 8;
            if (r_hi < rows) {
                __half2 v = __floats2half2_rn(acc[mt][nt][2], acc[mt][nt][3]);
                *(__half2*)(g_outs + (size_t)(row0 + r_hi) * HDIM + col) = v;
            }
        }
    }
}

// ---------------- combine: weighted unroute (fp16 g_outs) -------------------
__global__ void combine_kernel(const float* __restrict__ tw,
                               float* __restrict__ out) {
    const int HQ = HDIM / 4;
    int idx = blockIdx.x * blockDim.x + threadIdx.x;
    if (idx >= N_TOK * HQ) return;
    int n = idx / HQ;
    int hq = idx - n * HQ;
    int p0 = g_slot2pos[n * TOPK + 0];
    int p1 = g_slot2pos[n * TOPK + 1];
    float w0 = tw[n * TOPK + 0];
    float w1 = tw[n * TOPK + 1];
    uint2 a = ((const uint2*)(g_outs + (size_t)p0 * HDIM))[hq];
    uint2 b = ((const uint2*)(g_outs + (size_t)p1 * HDIM))[hq];
    float2 a0 = __half22float2(*(__half2*)&a.x);
    float2 a1 = __half22float2(*(__half2*)&a.y);
    float2 b0 = __half22float2(*(__half2*)&b.x);
    float2 b1 = __half22float2(*(__half2*)&b.y);
    float4 r;
    r.x = w0 * a0.x + w1 * b0.x;
    r.y = w0 * a0.y + w1 * b0.y;
    r.z = w0 * a1.x + w1 * b1.x;
    r.w = w0 * a1.y + w1 * b1.y;
    ((float4*)out)[idx] = r;
}

// ---------------- host ----------------
typedef CUresult (*encfn_t)(CUtensorMap*, CUtensorMapDataType, cuuint32_t, void*,
                            const cuuint64_t*, const cuuint64_t*, const cuuint32_t*,
                            const cuuint32_t*, CUtensorMapInterleave, CUtensorMapSwizzle,
                            CUtensorMapL2promotion, CUtensorMapFloatOOBfill);

static void enc_f16(encfn_t fn, CUtensorMap* m, void* p,
                    unsigned long long d0, unsigned long long d1, unsigned long long d2,
                    unsigned long long s1, unsigned long long s2, unsigned box1) {
    cuuint64_t dims[3] = {d0, d1, d2};
    cuuint64_t str[2]  = {s1, s2};
    cuuint32_t box[3]  = {KC, box1, 1};
    cuuint32_t es[3]   = {1, 1, 1};
    fn(m, CU_TENSOR_MAP_DATA_TYPE_FLOAT16, 3, p, dims, str, box, es,
       CU_TENSOR_MAP_INTERLEAVE_NONE, CU_TENSOR_MAP_SWIZZLE_128B,
       CU_TENSOR_MAP_L2_PROMOTION_L2_128B, CU_TENSOR_MAP_FLOAT_OOB_FILL_NONE);
}

extern "C" void kernel_launch(void* const* d_in, const int* in_sizes, int n_in,
                              void* d_out, int out_size) {
    const float* x  = (const float*)d_in[0];
    const int*   ti = (const int*)  d_in[1];
    const float* tw = (const float*)d_in[2];
    const float* gu = (const float*)d_in[3];
    const float* dn = (const float*)d_in[4];
    float* out = (float*)d_out;

    static cudaStream_t st1 = nullptr, st2 = nullptr;
    static cudaEvent_t evRoot, evW1, evW2;
    if (st1 == nullptr) {
        cudaStreamCreateWithFlags(&st1, cudaStreamNonBlocking);
        cudaStreamCreateWithFlags(&st2, cudaStreamNonBlocking);
        cudaEventCreateWithFlags(&evRoot, cudaEventDisableTiming);
        cudaEventCreateWithFlags(&evW1, cudaEventDisableTiming);
        cudaEventCreateWithFlags(&evW2, cudaEventDisableTiming);
    }

    void* fp = nullptr;
    cudaDriverEntryPointQueryResult qr;
    cudaGetDriverEntryPointByVersion("cuTensorMapEncodeTiled", &fp, 12000,
                                     cudaEnableDefault, &qr);
    encfn_t fn = (encfn_t)fp;

    void *pax, *pw1, *pw2, *pint;
    cudaGetSymbolAddress(&pax,  g_ax);
    cudaGetSymbolAddress(&pw1,  g_w1t);
    cudaGetSymbolAddress(&pw2,  g_w2t);
    cudaGetSymbolAddress(&pint, g_inter);

    CUtensorMap tA1, tB1, tA2, tB2;
    enc_f16(fn, &tA1, pax, HDIM, NSLOT, 1,
            (unsigned long long)HDIM * 2, (unsigned long long)HDIM * 2 * NSLOT, 128);
    enc_f16(fn, &tB1, pw1, HDIM, 2 * IDIM, NEXP,
            (unsigned long long)HDIM * 2, (unsigned long long)HDIM * 2 * 2 * IDIM, 64);
    enc_f16(fn, &tA2, pint, IDIM, NSLOT, 1,
            (unsigned long long)IDIM * 2, (unsigned long long)IDIM * 2 * NSLOT, 128);
    enc_f16(fn, &tB2, pw2, IDIM, HDIM, NEXP,
            (unsigned long long)IDIM * 2, (unsigned long long)IDIM * 2 * HDIM, 64);

    cudaFuncSetAttribute(gemm1_tc, cudaFuncAttributeMaxDynamicSharedMemorySize, SMEM_DYN);
    cudaFuncSetAttribute(gemm2_tc, cudaFuncAttributeMaxDynamicSharedMemorySize, SMEM_DYN);

    cudaStream_t s0 = (cudaStream_t)0;

    cudaEventRecord(evRoot, s0);
    cudaStreamWaitEvent(st1, evRoot, 0);
    cudaStreamWaitEvent(st2, evRoot, 0);
    transpose_w1_kernel<<<dim3(HDIM / 64, 2 * IDIM / 64, NEXP), 256, 0, st1>>>(gu);
    transpose_w2_kernel<<<dim3(IDIM / 64, HDIM / 64, NEXP), 256, 0, st2>>>(dn);

    route_kernel<<<1, 256, 0, s0>>>(ti);
    gather_x_kernel<<<NSLOT, 256, 0, s0>>>(x);

    cudaEventRecord(evW1, st1);
    cudaStreamWaitEvent(s0, evW1, 0);
    gemm1_tc<<<dim3(IDIM / 64, MAXT), 256, SMEM_DYN, s0>>>(tA1, tB1);

    cudaEventRecord(evW2, st2);
    cudaStreamWaitEvent(s0, evW2, 0);
    gemm2_tc<<<dim3(HDIM / 128, MAXT), 256, SMEM_DYN, s0>>>(tA2, tB2);

    combine_kernel<<<(N_TOK * (HDIM / 4) + 255) / 256, 256, 0, s0>>>(tw, out);
}